// round 16
// baseline (speedup 1.0000x reference)
#include <cuda_runtime.h>
#include <cuda_bf16.h>
#include <cstdint>

// ---------------------------------------------------------------------------
// BigramLM forward, GB300 sm_103a.  FUSED warp-private design (flush fixed):
//   build_qkv : QT/KT/VT tables + VF = VT@Wf+bf  (FF folded; 520 x 32 each)
//   build_bf  : Wl mma-fragment prepack (bf16 hi/lo) + bias table
//   build_qk  : EQK[pair(t,s)][tok_t][tok_s][h] = exp(q.k * 32^-0.5) (L2)
//   bigram_main: per warp (32 batches): scalar attention (row-paired VF
//     gathers, u64 smem loads) -> Y pair rows in smem (packed bf16 hi|lo),
//     warp-local m16n8k16 bf16 mma (3-product compensated split), ZT-staged
//     coalesced u64 output stores (65 u64 per batch-pair-row, FULLY covered).
//     NO block barriers in the main loop.
// ---------------------------------------------------------------------------

#define VOCAB   65
#define NEMB    32
#define TBLK    8
#define NPAIR   36
#define NTV     (TBLK*VOCAB)        // 520

typedef unsigned long long u64;
typedef unsigned int u32;

__device__ __align__(16) float g_QT[NTV * NEMB];
__device__ __align__(16) float g_KT[NTV * NEMB];
__device__ __align__(16) float g_VT[NTV * NEMB];
__device__ __align__(16) float g_VF[NTV * NEMB];
__device__ __align__(16) float g_QK[NPAIR * VOCAB * VOCAB * 4];
__device__ __align__(16) uint4 g_BF[576];
__device__ float g_BIAS[72];

// ---------------- packed f32x2 helpers --------------------------------------
__device__ __forceinline__ u64 pk2(float a, float b) {
    u64 r;
    asm("mov.b64 %0, {%1, %2};" : "=l"(r)
        : "r"(__float_as_uint(a)), "r"(__float_as_uint(b)));
    return r;
}
__device__ __forceinline__ void upk2(float& a, float& b, u64 p) {
    u32 x, y;
    asm("mov.b64 {%0, %1}, %2;" : "=r"(x), "=r"(y) : "l"(p));
    a = __uint_as_float(x); b = __uint_as_float(y);
}
__device__ __forceinline__ u64 fma2(u64 a, u64 b, u64 c) {
    u64 d;
    asm("fma.rn.f32x2 %0, %1, %2, %3;" : "=l"(d) : "l"(a), "l"(b), "l"(c));
    return d;
}
__device__ __forceinline__ u64 mul2(u64 a, u64 b) {
    u64 d;
    asm("mul.rn.f32x2 %0, %1, %2;" : "=l"(d) : "l"(a), "l"(b));
    return d;
}

// bf16 hi/lo split helpers -----------------------------------------------------
__device__ __forceinline__ u32 bf2u(__nv_bfloat162 h) {
    return *reinterpret_cast<u32*>(&h);
}
__device__ __forceinline__ uint4 pack_hilo4(float4 q) {
    __nv_bfloat162 h01 = __floats2bfloat162_rn(q.x, q.y);
    float2 f01 = __bfloat1622float2(h01);
    __nv_bfloat162 l01 = __floats2bfloat162_rn(q.x - f01.x, q.y - f01.y);
    __nv_bfloat162 h23 = __floats2bfloat162_rn(q.z, q.w);
    float2 f23 = __bfloat1622float2(h23);
    __nv_bfloat162 l23 = __floats2bfloat162_rn(q.z - f23.x, q.w - f23.y);
    u32 hu01 = bf2u(h01), lu01 = bf2u(l01);
    u32 hu23 = bf2u(h23), lu23 = bf2u(l23);
    uint4 r;
    r.x = __byte_perm(hu01, lu01, 0x5410);
    r.y = __byte_perm(hu01, lu01, 0x7632);
    r.z = __byte_perm(hu23, lu23, 0x5410);
    r.w = __byte_perm(hu23, lu23, 0x7632);
    return r;
}
__device__ __forceinline__ void mma16816(float* d, const u32* a,
                                         u32 b0, u32 b1) {
    asm volatile(
        "mma.sync.aligned.m16n8k16.row.col.f32.bf16.bf16.f32 "
        "{%0,%1,%2,%3}, {%4,%5,%6,%7}, {%8,%9}, {%0,%1,%2,%3};"
        : "+f"(d[0]), "+f"(d[1]), "+f"(d[2]), "+f"(d[3])
        : "r"(a[0]), "r"(a[1]), "r"(a[2]), "r"(a[3]), "r"(b0), "r"(b1));
}

// ---------------- stage 1: q/k/v tables + folded-FF VF ------------------------
__global__ void build_qkv(const float* __restrict__ tok_emb,
                          const float* __restrict__ pos_emb,
                          const float* __restrict__ Wq,
                          const float* __restrict__ Wk,
                          const float* __restrict__ Wv,
                          const float* __restrict__ Wf,
                          const float* __restrict__ bf) {
    __shared__ float vrow[NEMB];
    int tv = blockIdx.x;
    int t  = tv / VOCAB;
    int v  = tv - t * VOCAB;
    int f  = threadIdx.x;
    int h  = f >> 3, d = f & 7;
    float qa = 0.f, ka = 0.f, va = 0.f;
#pragma unroll
    for (int c = 0; c < NEMB; c++) {
        float x = tok_emb[v * NEMB + c] + pos_emb[t * NEMB + c];
        int wi = (h * NEMB + c) * 8 + d;
        qa = fmaf(x, Wq[wi], qa);
        ka = fmaf(x, Wk[wi], ka);
        va = fmaf(x, Wv[wi], va);
    }
    g_QT[tv * NEMB + f] = qa;
    g_KT[tv * NEMB + f] = ka;
    g_VT[tv * NEMB + f] = va;
    vrow[f] = va;
    __syncwarp();
    float acc = bf[f];
#pragma unroll
    for (int c = 0; c < NEMB; c++)
        acc = fmaf(vrow[c], Wf[c * NEMB + f], acc);
    g_VF[tv * NEMB + f] = acc;
}

// ---------------- Wl fragment prepack + bias ----------------------------------
__global__ void build_bf(const float* __restrict__ Wl,
                         const float* __restrict__ bl) {
    int e = blockIdx.x * blockDim.x + threadIdx.x;
    if (e < 576) {
        int lane = e & 31, kc = (e >> 5) & 1, nt = e >> 6;
        int g = lane >> 2, t = lane & 3;
        int n = nt * 8 + g;
        int k0 = kc * 16 + 2 * t;
        float w0 = (n < VOCAB) ? Wl[k0 * VOCAB + n] : 0.f;
        float w1 = (n < VOCAB) ? Wl[(k0 + 1) * VOCAB + n] : 0.f;
        float w2 = (n < VOCAB) ? Wl[(k0 + 8) * VOCAB + n] : 0.f;
        float w3 = (n < VOCAB) ? Wl[(k0 + 9) * VOCAB + n] : 0.f;
        __nv_bfloat162 h01 = __floats2bfloat162_rn(w0, w1);
        float2 f01 = __bfloat1622float2(h01);
        __nv_bfloat162 l01 = __floats2bfloat162_rn(w0 - f01.x, w1 - f01.y);
        __nv_bfloat162 h23 = __floats2bfloat162_rn(w2, w3);
        float2 f23 = __bfloat1622float2(h23);
        __nv_bfloat162 l23 = __floats2bfloat162_rn(w2 - f23.x, w3 - f23.y);
        g_BF[e] = make_uint4(bf2u(h01), bf2u(h23), bf2u(l01), bf2u(l23));
    }
    if (e < 72) g_BIAS[e] = (e < VOCAB) ? bl[e] : 0.f;
}

// ---------------- stage 2: exp(attention-logit) table -------------------------
__global__ void build_qk() {
    int P = blockIdx.y;
    int a = blockIdx.x;
    int t = 0, rem = P;
    while (rem > t) { rem -= (t + 1); t++; }
    int s = rem;
    const float scale = 0.17677669529663687f;   // 32^-0.5 (n_embed!)
    for (int u = threadIdx.x; u < VOCAB * 4; u += blockDim.x) {
        int b = u >> 2, h = u & 3;
        const float* qp = &g_QT[(t * VOCAB + a) * NEMB + h * 8];
        const float* kp = &g_KT[(s * VOCAB + b) * NEMB + h * 8];
        float acc = 0.f;
#pragma unroll
        for (int d = 0; d < 8; d++) acc = fmaf(qp[d], kp[d], acc);
        g_QK[((P * VOCAB + a) * VOCAB + b) * 4 + h] = __expf(acc * scale);
    }
}

// ============================== fused main kernel =============================
// smem (float units):
#define F_SVF   0                           // VF 520 x 34 (u64 accesses only!)
#define F_SY    (NTV * 34)                  // 17680 ; Y 512 rows x 36 u32
#define F_BF    (F_SY + 512 * 36)           // 36112 ; BF uint4[576]
#define F_BIAS  (F_BF + 576 * 4)            // 38416 ; bias 72
#define F_ZT    (F_BIAS + 72)               // 38488 ; ZT 8 warps x 16 x ZPAD
#define ZPAD    138
#define F_FLOATS (F_ZT + 8 * 16 * ZPAD)     // 56152
#define F_BYTES  (F_FLOATS * 4)             // 224608

template<int TA>
__device__ __forceinline__ void attn_pair(const float4* __restrict__ QK4,
                                          const float* __restrict__ smVF,
                                          const int* __restrict__ tok,
                                          u32* __restrict__ yrowA,
                                          u32* __restrict__ yrowB)
{
    constexpr int TB = TA + 1;
    const int baseA = TA * (TA + 1) / 2;
    const int baseB = baseA + TA + 1;
    const int rA = tok[TA] * VOCAB;
    const int rB = tok[TB] * VOCAB;

    float4 sA = make_float4(0.f, 0.f, 0.f, 0.f);
    float4 sB = make_float4(0.f, 0.f, 0.f, 0.f);
    u64 hA[16], hB[16];
#pragma unroll
    for (int g = 0; g < 16; g++) { hA[g] = 0ULL; hB[g] = 0ULL; }

    // shared-s combine: each VF row loaded ONCE for rows TA and TB (u64 LDS;
    // rows are 8B-aligned with pad 34 — NOT 16B, so no 128-bit loads here)
#pragma unroll
    for (int s = 0; s <= TA; s++) {
        float4 eA = __ldg(&QK4[(baseA + s) * (VOCAB * VOCAB) + rA + tok[s]]);
        float4 eB = __ldg(&QK4[(baseB + s) * (VOCAB * VOCAB) + rB + tok[s]]);
        sA.x += eA.x; sA.y += eA.y; sA.z += eA.z; sA.w += eA.w;
        sB.x += eB.x; sB.y += eB.y; sB.z += eB.z; sB.w += eB.w;
        u64 wA[4] = { pk2(eA.x, eA.x), pk2(eA.y, eA.y),
                      pk2(eA.z, eA.z), pk2(eA.w, eA.w) };
        u64 wB[4] = { pk2(eB.x, eB.x), pk2(eB.y, eB.y),
                      pk2(eB.z, eB.z), pk2(eB.w, eB.w) };
        const u64* v2 = (const u64*)(smVF + (s * VOCAB + tok[s]) * 34);
#pragma unroll
        for (int g = 0; g < 16; g++) {
            u64 r = v2[g];
            hA[g] = fma2(wA[g >> 2], r, hA[g]);
            hB[g] = fma2(wB[g >> 2], r, hB[g]);
        }
    }
    {   // extra s = TB term, row B only
        float4 eB = __ldg(&QK4[(baseB + TB) * (VOCAB * VOCAB) + rB + tok[TB]]);
        sB.x += eB.x; sB.y += eB.y; sB.z += eB.z; sB.w += eB.w;
        u64 wB[4] = { pk2(eB.x, eB.x), pk2(eB.y, eB.y),
                      pk2(eB.z, eB.z), pk2(eB.w, eB.w) };
        const u64* v2 = (const u64*)(smVF + (TB * VOCAB + tok[TB]) * 34);
#pragma unroll
        for (int g = 0; g < 16; g++)
            hB[g] = fma2(wB[g >> 2], v2[g], hB[g]);
    }

    u64 iA[4], iB[4];
    {
        float a = __fdividef(1.f, sA.x), b = __fdividef(1.f, sA.y);
        float c = __fdividef(1.f, sA.z), d = __fdividef(1.f, sA.w);
        iA[0] = pk2(a, a); iA[1] = pk2(b, b); iA[2] = pk2(c, c); iA[3] = pk2(d, d);
        a = __fdividef(1.f, sB.x); b = __fdividef(1.f, sB.y);
        c = __fdividef(1.f, sB.z); d = __fdividef(1.f, sB.w);
        iB[0] = pk2(a, a); iB[1] = pk2(b, b); iB[2] = pk2(c, c); iB[3] = pk2(d, d);
    }
#pragma unroll
    for (int g = 0; g < 8; g++) {
        float4 q;
        upk2(q.x, q.y, mul2(hA[2 * g],     iA[g >> 1]));
        upk2(q.z, q.w, mul2(hA[2 * g + 1], iA[g >> 1]));
        q.x = fmaxf(q.x, 0.f); q.y = fmaxf(q.y, 0.f);
        q.z = fmaxf(q.z, 0.f); q.w = fmaxf(q.w, 0.f);
        *(uint4*)(yrowA + 4 * g) = pack_hilo4(q);
    }
#pragma unroll
    for (int g = 0; g < 8; g++) {
        float4 q;
        upk2(q.x, q.y, mul2(hB[2 * g],     iB[g >> 1]));
        upk2(q.z, q.w, mul2(hB[2 * g + 1], iB[g >> 1]));
        q.x = fmaxf(q.x, 0.f); q.y = fmaxf(q.y, 0.f);
        q.z = fmaxf(q.z, 0.f); q.w = fmaxf(q.w, 0.f);
        *(uint4*)(yrowB + 4 * g) = pack_hilo4(q);
    }
}

// warp-local mma + staged flush for one row pair (T even)
__device__ __forceinline__ void mma_pair(float* __restrict__ sm,
                                         float* __restrict__ out,
                                         int T, int gbase, int nb,
                                         int wid, int lane)
{
    const u32*   smY  = (const u32*)(sm + F_SY);
    const uint4* BF   = (const uint4*)(sm + F_BF);
    const float* BIAS = sm + F_BIAS;
    float* ztw = sm + F_ZT + wid * (16 * ZPAD);

    int g = lane >> 2, t = lane & 3;

#pragma unroll
    for (int g16 = 0; g16 < 2; g16++) {
        int b0 = wid * 32 + g16 * 16;                // local batch base
        const u32* yA = smY + (size_t)b0 * 36;
        const u32* yB = smY + (size_t)(256 + b0) * 36;

        // ---- A fragments for both tiles (hi/lo via PRMT) ----
        u32 AhA[2][4], AlA[2][4], AhB[2][4], AlB[2][4];
#pragma unroll
        for (int kc = 0; kc < 2; kc++) {
            int c = kc * 16 + 2 * t;
            uint2 p;
            p = *(const uint2*)(yA + g * 36 + c);
            AhA[kc][0] = __byte_perm(p.x, p.y, 0x5410);
            AlA[kc][0] = __byte_perm(p.x, p.y, 0x7632);
            p = *(const uint2*)(yA + (g + 8) * 36 + c);
            AhA[kc][1] = __byte_perm(p.x, p.y, 0x5410);
            AlA[kc][1] = __byte_perm(p.x, p.y, 0x7632);
            p = *(const uint2*)(yA + g * 36 + c + 8);
            AhA[kc][2] = __byte_perm(p.x, p.y, 0x5410);
            AlA[kc][2] = __byte_perm(p.x, p.y, 0x7632);
            p = *(const uint2*)(yA + (g + 8) * 36 + c + 8);
            AhA[kc][3] = __byte_perm(p.x, p.y, 0x5410);
            AlA[kc][3] = __byte_perm(p.x, p.y, 0x7632);

            p = *(const uint2*)(yB + g * 36 + c);
            AhB[kc][0] = __byte_perm(p.x, p.y, 0x5410);
            AlB[kc][0] = __byte_perm(p.x, p.y, 0x7632);
            p = *(const uint2*)(yB + (g + 8) * 36 + c);
            AhB[kc][1] = __byte_perm(p.x, p.y, 0x5410);
            AlB[kc][1] = __byte_perm(p.x, p.y, 0x7632);
            p = *(const uint2*)(yB + g * 36 + c + 8);
            AhB[kc][2] = __byte_perm(p.x, p.y, 0x5410);
            AlB[kc][2] = __byte_perm(p.x, p.y, 0x7632);
            p = *(const uint2*)(yB + (g + 8) * 36 + c + 8);
            AhB[kc][3] = __byte_perm(p.x, p.y, 0x5410);
            AlB[kc][3] = __byte_perm(p.x, p.y, 0x7632);
        }

        // ---- 9 n-tiles x 2 k-chunks x 3 products ; stage into ZT ----
#pragma unroll
        for (int nt = 0; nt < 9; nt++) {
            float dA[4] = { 0.f, 0.f, 0.f, 0.f };
            float dB[4] = { 0.f, 0.f, 0.f, 0.f };
#pragma unroll
            for (int kc = 0; kc < 2; kc++) {
                uint4 bf = BF[(nt * 2 + kc) * 32 + lane];
                mma16816(dA, AhA[kc], bf.x, bf.y);
                mma16816(dA, AlA[kc], bf.x, bf.y);
                mma16816(dA, AhA[kc], bf.z, bf.w);
                mma16816(dB, AhB[kc], bf.x, bf.y);
                mma16816(dB, AlB[kc], bf.x, bf.y);
                mma16816(dB, AhB[kc], bf.z, bf.w);
            }
            int c0 = nt * 8 + 2 * t;
            if (c0 < VOCAB) {
                float bi0 = BIAS[c0];
                ztw[g * ZPAD + c0]            = dA[0] + bi0;
                ztw[(g + 8) * ZPAD + c0]      = dA[2] + bi0;
                ztw[g * ZPAD + 65 + c0]       = dB[0] + bi0;
                ztw[(g + 8) * ZPAD + 65 + c0] = dB[2] + bi0;
                if (c0 + 1 < VOCAB) {
                    float bi1 = BIAS[c0 + 1];
                    ztw[g * ZPAD + c0 + 1]            = dA[1] + bi1;
                    ztw[(g + 8) * ZPAD + c0 + 1]      = dA[3] + bi1;
                    ztw[g * ZPAD + 65 + c0 + 1]       = dB[1] + bi1;
                    ztw[(g + 8) * ZPAD + 65 + c0 + 1] = dB[3] + bi1;
                }
            }
        }
        __syncwarp();

        // ---- flush: 16 batches x 130 contiguous floats = 65 u64 each ----
#pragma unroll 4
        for (int i = 0; i < 16; i++) {
            int gb = gbase + b0 + i;
            if (gb < nb) {
                const u64* src = (const u64*)(ztw + i * ZPAD);
                u64* dst = (u64*)(out + (size_t)gb * 520 + T * 65);
#pragma unroll
                for (int j = 0; j < 3; j++) {
                    int e = j * 32 + lane;          // 0..95; need 0..64
                    if (e < 65) __stcs(dst + e, src[e]);
                }
            }
        }
        __syncwarp();
    }
}

__global__ void __launch_bounds__(256, 1) bigram_main(
        const int* __restrict__ idx, float* __restrict__ out, int nb) {
    extern __shared__ float sm[];
    int tid = threadIdx.x;
    int wid = tid >> 5, lane = tid & 31;

    // ---- cooperative init: VF, BF fragments, bias ----
    for (int r = tid; r < NTV; r += 256) {
        const u64* src = (const u64*)(g_VF + r * NEMB);
        u64* dst = (u64*)(sm + F_SVF + r * 34);
#pragma unroll
        for (int g = 0; g < 16; g++) dst[g] = src[g];
    }
    {
        uint4* BFs = (uint4*)(sm + F_BF);
        for (int e = tid; e < 576; e += 256) BFs[e] = g_BF[e];
        if (tid < 72) sm[F_BIAS + tid] = g_BIAS[tid];
    }
    __syncthreads();

    const float4* QK4 = (const float4*)g_QK;
    u32* smY = (u32*)(sm + F_SY);
    int ntile = (nb + 255) >> 8;

    for (int tile = blockIdx.x; tile < ntile; tile += gridDim.x) {
        int gbase = tile << 8;
        int b = gbase + tid;
        int bc = min(b, nb - 1);
        int tok[8];
        {
            const int4* pa = (const int4*)(idx + (size_t)bc * 8);
            int4 x0 = __ldg(pa), x1 = __ldg(pa + 1);
            tok[0] = x0.x; tok[1] = x0.y; tok[2] = x0.z; tok[3] = x0.w;
            tok[4] = x1.x; tok[5] = x1.y; tok[6] = x1.z; tok[7] = x1.w;
        }
        u32* yrowA = smY + (size_t)tid * 36;
        u32* yrowB = smY + (size_t)(tid + 256) * 36;

#define PAIR(T)                                                             \
        attn_pair<T>(QK4, sm + F_SVF, tok, yrowA, yrowB);                   \
        __syncwarp();                                                       \
        mma_pair(sm, out, T, gbase, nb, wid, lane);

        PAIR(0) PAIR(2) PAIR(4) PAIR(6)
#undef PAIR
    }
}

// ---------------------------------------------------------------------------
extern "C" void kernel_launch(void* const* d_in, const int* in_sizes, int n_in,
                              void* d_out, int out_size) {
    const int*   idx     = (const int*)  d_in[0];
    const float* tok_emb = (const float*)d_in[1];
    const float* pos_emb = (const float*)d_in[2];
    const float* Wq      = (const float*)d_in[3];
    const float* Wk      = (const float*)d_in[4];
    const float* Wv      = (const float*)d_in[5];
    const float* Wf      = (const float*)d_in[6];
    const float* bf      = (const float*)d_in[7];
    const float* Wl      = (const float*)d_in[8];
    const float* bl      = (const float*)d_in[9];
    float* out = (float*)d_out;

    int nb = in_sizes[0] / TBLK;   // 131072

    cudaFuncSetAttribute(bigram_main,
                         cudaFuncAttributeMaxDynamicSharedMemorySize, F_BYTES);

    int dev = 0, nsm = 148;
    cudaGetDevice(&dev);
    cudaDeviceGetAttribute(&nsm, cudaDevAttrMultiProcessorCount, dev);

    build_qkv<<<NTV, 32>>>(tok_emb, pos_emb, Wq, Wk, Wv, Wf, bf);
    build_bf<<<3, 256>>>(Wl, bl);
    build_qk<<<dim3(VOCAB, NPAIR), 256>>>();

    bigram_main<<<nsm, 256, F_BYTES>>>(idx, out, nb);
}